// round 15
// baseline (speedup 1.0000x reference)
#include <cuda_runtime.h>
#include <math.h>

#define Bsz 1024
#define Ssz 350
#define Vsz 41
#define BT 8
#define NCTA 128
#define NTHR 512

typedef unsigned long long u64;

// ---------------- persistent device scratch ----------------
__device__ float4 g_wA[49152];     // Whh0: [kc][gate][256]
__device__ float4 g_wB1[24576];    // Wih1: [kc][gate][128]
__device__ float4 g_wB2[12288];    // Whh1: [kc][gate][128]
__device__ float4 g_wC1[3072];     // Wih2: [kc][gate][32]
__device__ float4 g_wC2[768];      // Whh2: [kc][gate][32]
__device__ float  g_WprojT[1312];  // [k][j]
__device__ float  g_G0[41 * 768];  // [v][col]
__device__ float  g_Hinit[Bsz * 416];

// ---------------- f32x2 helpers ----------------
__device__ __forceinline__ u64 fma2(u64 a, u64 b, u64 c) {
    u64 d; asm("fma.rn.f32x2 %0,%1,%2,%3;" : "=l"(d) : "l"(a), "l"(b), "l"(c)); return d;
}
__device__ __forceinline__ u64 pk2(float x, float y) {
    u64 d; asm("mov.b64 %0,{%1,%2};" : "=l"(d) : "f"(x), "f"(y)); return d;
}
__device__ __forceinline__ void up2(u64 a, float& x, float& y) {
    asm("mov.b64 {%0,%1}, %2;" : "=f"(x), "=f"(y) : "l"(a));
}
__device__ __forceinline__ float sigf(float x) {
    return __fdividef(1.0f, 1.0f + __expf(-x));
}
__device__ __forceinline__ float tanh_(float x) {
    float ax = fabsf(x);
    float e = __expf(-2.0f * ax);
    float t = __fdividef(1.0f - e, 1.0f + e);
    return copysignf(t, x);
}

// ---------------- fused prep kernel (identical to R12) ----------------
__global__ void k_prep(const float* __restrict__ latent, const float* __restrict__ W_emb,
                       const float* __restrict__ b_emb, const float* __restrict__ W_init,
                       const float* __restrict__ b_init, const float* __restrict__ Wih0,
                       const float* __restrict__ bih0, const float* __restrict__ Whh0,
                       const float* __restrict__ Wih1, const float* __restrict__ Whh1,
                       const float* __restrict__ Wih2, const float* __restrict__ Whh2,
                       const float* __restrict__ W_proj) {
    const int b = blockIdx.x, tid = threadIdx.x;
    const int PTH = 256;
    if (b < 128) {
        __shared__ float lat[8 * 512];
        const int b0 = b * 8;
        for (int i = tid; i < 8 * 512; i += PTH) lat[i] = latent[(size_t)b0 * 512 + i];
        __syncthreads();
        for (int c = tid; c < 416; c += PTH) {
            float acc[8];
            float bi = b_init[c];
#pragma unroll
            for (int r = 0; r < 8; r++) acc[r] = bi;
            const float* w = W_init + (size_t)c * 512;
            for (int k = 0; k < 512; k += 4) {
                float4 wv = *(const float4*)(w + k);
#pragma unroll
                for (int r = 0; r < 8; r++) {
                    acc[r] += wv.x * lat[r * 512 + k];
                    acc[r] += wv.y * lat[r * 512 + k + 1];
                    acc[r] += wv.z * lat[r * 512 + k + 2];
                    acc[r] += wv.w * lat[r * 512 + k + 3];
                }
            }
#pragma unroll
            for (int r = 0; r < 8; r++) g_Hinit[(size_t)(b0 + r) * 416 + c] = acc[r];
        }
    } else if (b < 169) {
        const int v = b - 128;
        __shared__ float emb[512];
        for (int k = tid; k < 512; k += PTH) emb[k] = W_emb[k * Vsz + v] + b_emb[k];
        __syncthreads();
        for (int j = tid; j < 768; j += PTH) {
            float acc = bih0[j];
            const float* w = Wih0 + (size_t)j * 512;
            for (int k = 0; k < 512; k += 4) {
                float4 wv = *(const float4*)(w + k);
                acc += wv.x * emb[k] + wv.y * emb[k + 1] + wv.z * emb[k + 2] + wv.w * emb[k + 3];
            }
            g_G0[v * 768 + j] = acc;
        }
    } else {
        const int TOTAL = 90184;
        for (int i = (b - 169) * PTH + tid; i < TOTAL; i += 87 * PTH) {
            if (i < 49152) {
                int kc = i / 768, rem = i % 768;
                g_wA[i] = *(const float4*)&Whh0[(size_t)rem * 256 + 4 * kc];
            } else if (i < 73728) {
                int t = i - 49152;
                int kc = t / 384, row = t % 384;
                g_wB1[t] = *(const float4*)&Wih1[(size_t)row * 256 + 4 * kc];
            } else if (i < 86016) {
                int t = i - 73728;
                int kc = t / 384, row = t % 384;
                g_wB2[t] = *(const float4*)&Whh1[(size_t)row * 128 + 4 * kc];
            } else if (i < 89088) {
                int t = i - 86016;
                int kc = t / 96, row = t % 96;
                g_wC1[t] = *(const float4*)&Wih2[(size_t)row * 128 + 4 * kc];
            } else if (i < 89856) {
                int t = i - 89088;
                int kc = t / 96, row = t % 96;
                g_wC2[t] = *(const float4*)&Whh2[(size_t)row * 32 + 4 * kc];
            } else {
                int t2 = i - 89856;
#pragma unroll
                for (int c = 0; c < 4; c++) {
                    int e = t2 * 4 + c;
                    if (e < 1312) {
                        int k = e / Vsz, j = e - k * Vsz;
                        g_WprojT[e] = W_proj[j * 32 + k];
                    }
                }
            }
        }
    }
}

// ---------------- main persistent GRU kernel (in-warp row split, 512 threads) ----------------
__global__ __launch_bounds__(NTHR, 1)
void k_main(const int* __restrict__ tokens,
            const float* __restrict__ bhh0,
            const float* __restrict__ bih1, const float* __restrict__ bhh1,
            const float* __restrict__ bih2, const float* __restrict__ bhh2,
            const float* __restrict__ b_proj,
            float* __restrict__ out, float* __restrict__ pred) {
    __shared__ __align__(16) u64 hrp0[256 * 4];
    __shared__ __align__(16) u64 hrp1[128 * 4];
    __shared__ __align__(16) u64 hrp2[32 * 4];
    __shared__ float lg[BT][44];
    __shared__ int toksAll[Ssz * 8];

    const int tid = threadIdx.x;
    const int b0 = blockIdx.x * BT;
    // Phase A role: column tA, row-half hf (lanes 2i/2i+1 share a column)
    const int tA = tid >> 1;
    const int rpA = (tid & 1) * 2;
    // Phase B role: column jjB, row-quarter qB (4 lanes share a column)
    const int jjB = tid >> 2;
    const int qB = tid & 3;
    // Phase C role (tid < 128)
    const int jc = tid & 31;
    const int qC = (tid >> 5) & 3;

    for (int i = tid; i < Ssz * 8; i += NTHR) {
        int stt = i >> 3, row = i & 7;
        toksAll[i] = (stt == 0) ? 1 : tokens[(size_t)(b0 + row) * Ssz + stt];
    }
    for (int idx = tid; idx < BT * 416; idx += NTHR) {
        int row = idx / 416, c = idx - row * 416;
        float v = g_Hinit[(size_t)(b0 + row) * 416 + c];
        if (c < 256)      ((float*)hrp0)[c * 8 + row] = v;
        else if (c < 384) ((float*)hrp1)[(c - 256) * 8 + row] = v;
        else              ((float*)hrp2)[(c - 384) * 8 + row] = v;
    }

    // biases
    const float bR0 = bhh0[tA], bZ0 = bhh0[256 + tA], bN0 = bhh0[512 + tA];
    const u64 bN0d = pk2(bN0, bN0);
    const u64 bBr = pk2(bih1[jjB] + bhh1[jjB], bih1[jjB] + bhh1[jjB]);
    const u64 bBz = pk2(bih1[128 + jjB] + bhh1[128 + jjB], bih1[128 + jjB] + bhh1[128 + jjB]);
    const u64 bBi = pk2(bih1[256 + jjB], bih1[256 + jjB]);
    const u64 bBh = pk2(bhh1[256 + jjB], bhh1[256 + jjB]);
    const u64 bCr = pk2(bih2[jc] + bhh2[jc], bih2[jc] + bhh2[jc]);
    const u64 bCz = pk2(bih2[32 + jc] + bhh2[32 + jc], bih2[32 + jc] + bhh2[32 + jc]);
    const u64 bCi = pk2(bih2[64 + jc], bih2[64 + jc]);
    const u64 bCh = pk2(bhh2[64 + jc], bhh2[64 + jc]);

    const float4* wAp = g_wA + tA;
    const float4* wB1p = g_wB1 + jjB;
    const float4* wB2p = g_wB2 + jjB;
    const float4* wC1p = g_wC1 + jc;
    const float4* wC2p = g_wC2 + jc;

    __syncthreads();

    for (int st = 0; st < Ssz; st++) {
        const int* tokrow = toksAll + st * 8;

        // ======== Phase A: col tA, rows rpA..rpA+1 (pairs), 2-deep pipelined ========
        {
            u64 aR[2], aZ[2], aN[2];
#pragma unroll
            for (int i = 0; i < 2; i++) {
                int rp = rpA + i;
                const float* ge = g_G0 + (size_t)tokrow[2 * rp] * 768;
                const float* go = g_G0 + (size_t)tokrow[2 * rp + 1] * 768;
                aR[i] = pk2(ge[tA] + bR0, go[tA] + bR0);
                aZ[i] = pk2(ge[256 + tA] + bZ0, go[256 + tA] + bZ0);
                aN[i] = bN0d;
            }
            float4 wr0 = wAp[0], wz0 = wAp[256], wn0 = wAp[512];
            float4 wr1 = wAp[768], wz1 = wAp[768 + 256], wn1 = wAp[768 + 512];
            for (int kc = 0; kc < 64; kc += 2) {
                int p2 = ((kc + 2) & 63) * 768, p3 = ((kc + 3) & 63) * 768;
                float4 nr0 = wAp[p2], nz0 = wAp[p2 + 256], nn0 = wAp[p2 + 512];
                float4 nr1 = wAp[p3], nz1 = wAp[p3 + 256], nn1 = wAp[p3 + 512];
#pragma unroll
                for (int half = 0; half < 2; half++) {
                    float4 wr = half ? wr1 : wr0;
                    float4 wz = half ? wz1 : wz0;
                    float4 wn = half ? wn1 : wn0;
                    const float wrr[4] = {wr.x, wr.y, wr.z, wr.w};
                    const float wzz[4] = {wz.x, wz.y, wz.z, wz.w};
                    const float wnn[4] = {wn.x, wn.y, wn.z, wn.w};
#pragma unroll
                    for (int c = 0; c < 4; c++) {
                        int k = 4 * (kc + half) + c;
                        ulonglong2 hA = *(const ulonglong2*)&hrp0[k * 4 + rpA];
                        u64 wrd = pk2(wrr[c], wrr[c]);
                        u64 wzd = pk2(wzz[c], wzz[c]);
                        u64 wnd = pk2(wnn[c], wnn[c]);
                        aR[0] = fma2(wrd, hA.x, aR[0]); aR[1] = fma2(wrd, hA.y, aR[1]);
                        aZ[0] = fma2(wzd, hA.x, aZ[0]); aZ[1] = fma2(wzd, hA.y, aZ[1]);
                        aN[0] = fma2(wnd, hA.x, aN[0]); aN[1] = fma2(wnd, hA.y, aN[1]);
                    }
                }
                wr0 = nr0; wz0 = nz0; wn0 = nn0;
                wr1 = nr1; wz1 = nz1; wn1 = nn1;
            }
            __syncthreads();
#pragma unroll
            for (int i = 0; i < 2; i++) {
                int rp = rpA + i;
                float r0e, r1e, z0e, z1e, n0e, n1e, h0e, h1e;
                up2(aR[i], r0e, r1e); up2(aZ[i], z0e, z1e); up2(aN[i], n0e, n1e);
                float gi0 = g_G0[(size_t)tokrow[2 * rp] * 768 + 512 + tA];
                float gi1 = g_G0[(size_t)tokrow[2 * rp + 1] * 768 + 512 + tA];
                up2(hrp0[tA * 4 + rp], h0e, h1e);
                float rg0 = sigf(r0e), rg1 = sigf(r1e);
                float zg0 = sigf(z0e), zg1 = sigf(z1e);
                float ng0 = tanh_(gi0 + rg0 * n0e), ng1 = tanh_(gi1 + rg1 * n1e);
                float v0 = (1.0f - zg0) * ng0 + zg0 * h0e;
                float v1 = (1.0f - zg1) * ng1 + zg1 * h1e;
                hrp0[tA * 4 + rp] = pk2(v0, v1);
            }
            __syncthreads();
        }

        // ======== Phase B: col jjB, row-pair qB, 2-deep pipelined ========
        {
            u64 rB = bBr, zB = bBz, iB = bBi, hB = bBh;
            {
                float4 wr0 = wB1p[0], wz0 = wB1p[128], wn0 = wB1p[256];
                float4 wr1 = wB1p[384], wz1 = wB1p[384 + 128], wn1 = wB1p[384 + 256];
                for (int kc = 0; kc < 64; kc += 2) {
                    int p2 = ((kc + 2) & 63) * 384, p3 = ((kc + 3) & 63) * 384;
                    float4 nr0 = wB1p[p2], nz0 = wB1p[p2 + 128], nn0 = wB1p[p2 + 256];
                    float4 nr1 = wB1p[p3], nz1 = wB1p[p3 + 128], nn1 = wB1p[p3 + 256];
#pragma unroll
                    for (int half = 0; half < 2; half++) {
                        float4 wr = half ? wr1 : wr0;
                        float4 wz = half ? wz1 : wz0;
                        float4 wn = half ? wn1 : wn0;
                        const float wrr[4] = {wr.x, wr.y, wr.z, wr.w};
                        const float wzz[4] = {wz.x, wz.y, wz.z, wz.w};
                        const float wnn[4] = {wn.x, wn.y, wn.z, wn.w};
#pragma unroll
                        for (int c = 0; c < 4; c++) {
                            int k = 4 * (kc + half) + c;
                            u64 h = hrp0[k * 4 + qB];
                            rB = fma2(pk2(wrr[c], wrr[c]), h, rB);
                            zB = fma2(pk2(wzz[c], wzz[c]), h, zB);
                            iB = fma2(pk2(wnn[c], wnn[c]), h, iB);
                        }
                    }
                    wr0 = nr0; wz0 = nz0; wn0 = nn0;
                    wr1 = nr1; wz1 = nz1; wn1 = nn1;
                }
            }
            {
                float4 wr0 = wB2p[0], wz0 = wB2p[128], wn0 = wB2p[256];
                float4 wr1 = wB2p[384], wz1 = wB2p[384 + 128], wn1 = wB2p[384 + 256];
                for (int kc = 0; kc < 32; kc += 2) {
                    int p2 = ((kc + 2) & 31) * 384, p3 = ((kc + 3) & 31) * 384;
                    float4 nr0 = wB2p[p2], nz0 = wB2p[p2 + 128], nn0 = wB2p[p2 + 256];
                    float4 nr1 = wB2p[p3], nz1 = wB2p[p3 + 128], nn1 = wB2p[p3 + 256];
#pragma unroll
                    for (int half = 0; half < 2; half++) {
                        float4 wr = half ? wr1 : wr0;
                        float4 wz = half ? wz1 : wz0;
                        float4 wn = half ? wn1 : wn0;
                        const float wrr[4] = {wr.x, wr.y, wr.z, wr.w};
                        const float wzz[4] = {wz.x, wz.y, wz.z, wz.w};
                        const float wnn[4] = {wn.x, wn.y, wn.z, wn.w};
#pragma unroll
                        for (int c = 0; c < 4; c++) {
                            int k = 4 * (kc + half) + c;
                            u64 h = hrp1[k * 4 + qB];
                            rB = fma2(pk2(wrr[c], wrr[c]), h, rB);
                            zB = fma2(pk2(wzz[c], wzz[c]), h, zB);
                            hB = fma2(pk2(wnn[c], wnn[c]), h, hB);
                        }
                    }
                    wr0 = nr0; wz0 = nz0; wn0 = nn0;
                    wr1 = nr1; wz1 = nz1; wn1 = nn1;
                }
            }
            __syncthreads();
            {
                float r0e, r1e, z0e, z1e, i0e, i1e, n0e, n1e, h0e, h1e;
                up2(rB, r0e, r1e); up2(zB, z0e, z1e);
                up2(iB, i0e, i1e); up2(hB, n0e, n1e);
                up2(hrp1[jjB * 4 + qB], h0e, h1e);
                float rg0 = sigf(r0e), rg1 = sigf(r1e);
                float zg0 = sigf(z0e), zg1 = sigf(z1e);
                float ng0 = tanh_(i0e + rg0 * n0e), ng1 = tanh_(i1e + rg1 * n1e);
                float v0 = (1.0f - zg0) * ng0 + zg0 * h0e;
                float v1 = (1.0f - zg1) * ng1 + zg1 * h1e;
                hrp1[jjB * 4 + qB] = pk2(v0, v1);
            }
            __syncthreads();
        }

        // ======== Phase C: layer 2 (tid < 128) ========
        if (tid < 128) {
            u64 rC = bCr, zC = bCz, iC = bCi, hC = bCh;
            for (int kc = 0; kc < 32; kc++) {
                float4 wr = wC1p[kc * 96];
                float4 wz = wC1p[kc * 96 + 32];
                float4 wn = wC1p[kc * 96 + 64];
                const float wrr[4] = {wr.x, wr.y, wr.z, wr.w};
                const float wzz[4] = {wz.x, wz.y, wz.z, wz.w};
                const float wnn[4] = {wn.x, wn.y, wn.z, wn.w};
#pragma unroll
                for (int c = 0; c < 4; c++) {
                    u64 h = hrp1[(4 * kc + c) * 4 + qC];
                    rC = fma2(pk2(wrr[c], wrr[c]), h, rC);
                    zC = fma2(pk2(wzz[c], wzz[c]), h, zC);
                    iC = fma2(pk2(wnn[c], wnn[c]), h, iC);
                }
            }
            for (int kc = 0; kc < 8; kc++) {
                float4 wr = wC2p[kc * 96];
                float4 wz = wC2p[kc * 96 + 32];
                float4 wn = wC2p[kc * 96 + 64];
                const float wrr[4] = {wr.x, wr.y, wr.z, wr.w};
                const float wzz[4] = {wz.x, wz.y, wz.z, wz.w};
                const float wnn[4] = {wn.x, wn.y, wn.z, wn.w};
#pragma unroll
                for (int c = 0; c < 4; c++) {
                    u64 h = hrp2[(4 * kc + c) * 4 + qC];
                    rC = fma2(pk2(wrr[c], wrr[c]), h, rC);
                    zC = fma2(pk2(wzz[c], wzz[c]), h, zC);
                    hC = fma2(pk2(wnn[c], wnn[c]), h, hC);
                }
            }
            __syncthreads();
            {
                float r0e, r1e, z0e, z1e, i0e, i1e, n0e, n1e, h0e, h1e;
                up2(rC, r0e, r1e); up2(zC, z0e, z1e);
                up2(iC, i0e, i1e); up2(hC, n0e, n1e);
                up2(hrp2[jc * 4 + qC], h0e, h1e);
                float rg0 = sigf(r0e), rg1 = sigf(r1e);
                float zg0 = sigf(z0e), zg1 = sigf(z1e);
                float ng0 = tanh_(i0e + rg0 * n0e), ng1 = tanh_(i1e + rg1 * n1e);
                float v0 = (1.0f - zg0) * ng0 + zg0 * h0e;
                float v1 = (1.0f - zg1) * ng1 + zg1 * h1e;
                hrp2[jc * 4 + qC] = pk2(v0, v1);
            }
        } else {
            __syncthreads();
        }
        __syncthreads();

        // ======== Phase D: projection + argmax (328 items, single pass) ========
        if (tid < BT * Vsz) {
            const float* h2f = (const float*)hrp2;
            int row = tid / Vsz, j = tid - row * Vsz;
            float acc = b_proj[j];
#pragma unroll
            for (int k = 0; k < 32; k++)
                acc += g_WprojT[k * Vsz + j] * h2f[k * 8 + row];
            out[((size_t)(b0 + row) * Ssz + st) * Vsz + j] = acc;
            lg[row][j] = acc;
        }
        __syncthreads();
        if (tid < BT && pred) {
            float best = lg[tid][0];
            int bi = 0;
#pragma unroll 1
            for (int j = 1; j < Vsz; j++) {
                float v = lg[tid][j];
                if (v > best) { best = v; bi = j; }
            }
            pred[(size_t)(b0 + tid) * Ssz + st] = (float)bi;
        }
        __syncthreads();
    }
}

// ---------------- launch ----------------
extern "C" void kernel_launch(void* const* d_in, const int* in_sizes, int n_in,
                              void* d_out, int out_size) {
    const float* latent  = (const float*)d_in[0];
    const int*   tokens  = (const int*)d_in[1];
    const float* W_emb   = (const float*)d_in[2];
    const float* b_emb   = (const float*)d_in[3];
    const float* W_init  = (const float*)d_in[4];
    const float* b_init  = (const float*)d_in[5];
    const float* Wih0    = (const float*)d_in[6];
    const float* Whh0    = (const float*)d_in[7];
    const float* bih0    = (const float*)d_in[8];
    const float* bhh0    = (const float*)d_in[9];
    const float* Wih1    = (const float*)d_in[10];
    const float* Whh1    = (const float*)d_in[11];
    const float* bih1    = (const float*)d_in[12];
    const float* bhh1    = (const float*)d_in[13];
    const float* Wih2    = (const float*)d_in[14];
    const float* Whh2    = (const float*)d_in[15];
    const float* bih2    = (const float*)d_in[16];
    const float* bhh2    = (const float*)d_in[17];
    const float* W_proj  = (const float*)d_in[18];
    const float* b_proj  = (const float*)d_in[19];

    float* out = (float*)d_out;
    size_t logits_elems = (size_t)Bsz * Ssz * Vsz;
    float* pred = ((size_t)out_size >= logits_elems + (size_t)Bsz * Ssz)
                      ? out + logits_elems : nullptr;

    k_prep<<<256, 256>>>(latent, W_emb, b_emb, W_init, b_init, Wih0, bih0, Whh0,
                         Wih1, Whh1, Wih2, Whh2, W_proj);
    k_main<<<NCTA, NTHR>>>(tokens, bhh0, bih1, bhh1, bih2, bhh2, b_proj, out, pred);
}

// round 16
// speedup vs baseline: 1.1370x; 1.1370x over previous
#include <cuda_runtime.h>
#include <math.h>

#define Bsz 1024
#define Ssz 350
#define Vsz 41
#define BT 8
#define NCTA 128
#define NTHR 384

typedef unsigned long long u64;

// ---------------- persistent device scratch ----------------
__device__ float4 g_wA[49152];     // Whh0: [kc][gate][256]
__device__ float4 g_wB1[24576];    // Wih1: [kc][gate][128]
__device__ float4 g_wB2[12288];    // Whh1: [kc][gate][128]
__device__ float4 g_wC1[3072];     // Wih2: [kc][gate][32]
__device__ float4 g_wC2[768];      // Whh2: [kc][gate][32]
__device__ float  g_WprojT[1312];  // [k][j]
__device__ float  g_G0[41 * 768];  // [v][col]
__device__ float  g_Hinit[Bsz * 416];

// ---------------- f32x2 helpers ----------------
__device__ __forceinline__ u64 fma2(u64 a, u64 b, u64 c) {
    u64 d; asm("fma.rn.f32x2 %0,%1,%2,%3;" : "=l"(d) : "l"(a), "l"(b), "l"(c)); return d;
}
__device__ __forceinline__ u64 pk2(float x, float y) {
    u64 d; asm("mov.b64 %0,{%1,%2};" : "=l"(d) : "f"(x), "f"(y)); return d;
}
__device__ __forceinline__ void up2(u64 a, float& x, float& y) {
    asm("mov.b64 {%0,%1}, %2;" : "=f"(x), "=f"(y) : "l"(a));
}
__device__ __forceinline__ float sigf(float x) {
    return __fdividef(1.0f, 1.0f + __expf(-x));
}
__device__ __forceinline__ float tanh_(float x) {
    float ax = fabsf(x);
    float e = __expf(-2.0f * ax);
    float t = __fdividef(1.0f - e, 1.0f + e);
    return copysignf(t, x);
}

// ---------------- fused prep kernel (identical to R12) ----------------
__global__ void k_prep(const float* __restrict__ latent, const float* __restrict__ W_emb,
                       const float* __restrict__ b_emb, const float* __restrict__ W_init,
                       const float* __restrict__ b_init, const float* __restrict__ Wih0,
                       const float* __restrict__ bih0, const float* __restrict__ Whh0,
                       const float* __restrict__ Wih1, const float* __restrict__ Whh1,
                       const float* __restrict__ Wih2, const float* __restrict__ Whh2,
                       const float* __restrict__ W_proj) {
    const int b = blockIdx.x, tid = threadIdx.x;
    const int PTH = 256;
    if (b < 128) {
        __shared__ float lat[8 * 512];
        const int b0 = b * 8;
        for (int i = tid; i < 8 * 512; i += PTH) lat[i] = latent[(size_t)b0 * 512 + i];
        __syncthreads();
        for (int c = tid; c < 416; c += PTH) {
            float acc[8];
            float bi = b_init[c];
#pragma unroll
            for (int r = 0; r < 8; r++) acc[r] = bi;
            const float* w = W_init + (size_t)c * 512;
            for (int k = 0; k < 512; k += 4) {
                float4 wv = *(const float4*)(w + k);
#pragma unroll
                for (int r = 0; r < 8; r++) {
                    acc[r] += wv.x * lat[r * 512 + k];
                    acc[r] += wv.y * lat[r * 512 + k + 1];
                    acc[r] += wv.z * lat[r * 512 + k + 2];
                    acc[r] += wv.w * lat[r * 512 + k + 3];
                }
            }
#pragma unroll
            for (int r = 0; r < 8; r++) g_Hinit[(size_t)(b0 + r) * 416 + c] = acc[r];
        }
    } else if (b < 169) {
        const int v = b - 128;
        __shared__ float emb[512];
        for (int k = tid; k < 512; k += PTH) emb[k] = W_emb[k * Vsz + v] + b_emb[k];
        __syncthreads();
        for (int j = tid; j < 768; j += PTH) {
            float acc = bih0[j];
            const float* w = Wih0 + (size_t)j * 512;
            for (int k = 0; k < 512; k += 4) {
                float4 wv = *(const float4*)(w + k);
                acc += wv.x * emb[k] + wv.y * emb[k + 1] + wv.z * emb[k + 2] + wv.w * emb[k + 3];
            }
            g_G0[v * 768 + j] = acc;
        }
    } else {
        const int TOTAL = 90184;
        for (int i = (b - 169) * PTH + tid; i < TOTAL; i += 87 * PTH) {
            if (i < 49152) {
                int kc = i / 768, rem = i % 768;
                g_wA[i] = *(const float4*)&Whh0[(size_t)rem * 256 + 4 * kc];
            } else if (i < 73728) {
                int t = i - 49152;
                int kc = t / 384, row = t % 384;
                g_wB1[t] = *(const float4*)&Wih1[(size_t)row * 256 + 4 * kc];
            } else if (i < 86016) {
                int t = i - 73728;
                int kc = t / 384, row = t % 384;
                g_wB2[t] = *(const float4*)&Whh1[(size_t)row * 128 + 4 * kc];
            } else if (i < 89088) {
                int t = i - 86016;
                int kc = t / 96, row = t % 96;
                g_wC1[t] = *(const float4*)&Wih2[(size_t)row * 128 + 4 * kc];
            } else if (i < 89856) {
                int t = i - 89088;
                int kc = t / 96, row = t % 96;
                g_wC2[t] = *(const float4*)&Whh2[(size_t)row * 32 + 4 * kc];
            } else {
                int t2 = i - 89856;
#pragma unroll
                for (int c = 0; c < 4; c++) {
                    int e = t2 * 4 + c;
                    if (e < 1312) {
                        int k = e / Vsz, j = e - k * Vsz;
                        g_WprojT[e] = W_proj[j * 32 + k];
                    }
                }
            }
        }
    }
}

// ---------------- main persistent GRU kernel (384 thr: A col-owner + B/C gate-col) ----------------
__global__ __launch_bounds__(NTHR, 1)
void k_main(const int* __restrict__ tokens,
            const float* __restrict__ bhh0,
            const float* __restrict__ bih1, const float* __restrict__ bhh1,
            const float* __restrict__ bih2, const float* __restrict__ bhh2,
            const float* __restrict__ b_proj,
            float* __restrict__ out, float* __restrict__ pred) {
    __shared__ __align__(16) u64 hrp0[256 * 4];
    __shared__ __align__(16) u64 hrp1[128 * 4];
    __shared__ __align__(16) u64 hrp2[32 * 4];
    __shared__ __align__(16) u64 cmb[1536];    // B/C gate partial exchange
    __shared__ __align__(16) u64 bhn[512];     // B hN partials
    __shared__ __align__(16) u64 chn[128];     // C hN partials
    __shared__ float lg[BT][44];
    __shared__ int toksAll[Ssz * 8];

    const int tid = threadIdx.x;
    const int b0 = blockIdx.x * BT;
    const int tA = (tid < 256) ? tid : 0;      // phase A column
    const int gB = tid >> 7;                   // window2 gate 0..2
    const int jB = tid & 127;                  // window2 column

    for (int i = tid; i < Ssz * 8; i += NTHR) {
        int stt = i >> 3, row = i & 7;
        toksAll[i] = (stt == 0) ? 1 : tokens[(size_t)(b0 + row) * Ssz + stt];
    }
    for (int idx = tid; idx < BT * 416; idx += NTHR) {
        int row = idx / 416, c = idx - row * 416;
        float v = g_Hinit[(size_t)(b0 + row) * 416 + c];
        if (c < 256)      ((float*)hrp0)[c * 8 + row] = v;
        else if (c < 384) ((float*)hrp1)[(c - 256) * 8 + row] = v;
        else              ((float*)hrp2)[(c - 384) * 8 + row] = v;
    }

    // biases
    const float bR0 = bhh0[tA], bZ0 = bhh0[256 + tA], bN0 = bhh0[512 + tA];
    const u64 bN0d = pk2(bN0, bN0);
    float bBsum;                                // window2 bias (r/z) or iN bias (n)
    if (gB < 2) bBsum = bih1[gB * 128 + jB] + bhh1[gB * 128 + jB];
    else        bBsum = bih1[256 + jB];
    const u64 bBd = pk2(bBsum, bBsum);
    const float bhnf = bhh1[256 + jB];          // used by window1 hN threads (jB = tid-256 when tid>=256 -> tid&127)
    const u64 bhnd = pk2(bhnf, bhnf);
    // window3 (tid<96): gate gC, col jC
    const int gb3 = tid >> 5, jb3 = tid & 31;
    float bCsum;
    if (gb3 < 2) bCsum = bih2[gb3 * 32 + jb3] + bhh2[gb3 * 32 + jb3];
    else         bCsum = bih2[64 + jb3];
    const u64 bCd = pk2(bCsum, bCsum);
    const float bchf = bhh2[64 + jb3];
    const u64 bchd = pk2(bchf, bchf);

    const float4* wAp = g_wA + tA;
    const float4* wB1p = g_wB1 + tid;           // gate-col = tid (window2)
    const float4* wB2p = g_wB2 + tid;
    const float4* wB2n = g_wB2 + 256 + jB;      // n-gate col (window1 hN threads)
    const float4* wC1p = g_wC1 + tid;           // tid<96
    const float4* wC2p = g_wC2 + tid;

    __syncthreads();

    for (int st = 0; st < Ssz; st++) {
        const int* tokrow = toksAll + st * 8;

        // ======== Window 1: Phase A accum (t<256) || B-hN + C-hN (t>=256) ========
        u64 aR[4], aZ[4], aN[4];
        if (tid < 256) {
#pragma unroll
            for (int rp = 0; rp < 4; rp++) {
                const float* ge = g_G0 + (size_t)tokrow[2 * rp] * 768;
                const float* go = g_G0 + (size_t)tokrow[2 * rp + 1] * 768;
                aR[rp] = pk2(ge[tA] + bR0, go[tA] + bR0);
                aZ[rp] = pk2(ge[256 + tA] + bZ0, go[256 + tA] + bZ0);
                aN[rp] = bN0d;
            }
            float4 wr0 = wAp[0], wz0 = wAp[256], wn0 = wAp[512];
            float4 wr1 = wAp[768], wz1 = wAp[768 + 256], wn1 = wAp[768 + 512];
            for (int kc = 0; kc < 64; kc += 2) {
                int p2 = ((kc + 2) & 63) * 768, p3 = ((kc + 3) & 63) * 768;
                float4 nr0 = wAp[p2], nz0 = wAp[p2 + 256], nn0 = wAp[p2 + 512];
                float4 nr1 = wAp[p3], nz1 = wAp[p3 + 256], nn1 = wAp[p3 + 512];
#pragma unroll
                for (int half = 0; half < 2; half++) {
                    float4 wr = half ? wr1 : wr0;
                    float4 wz = half ? wz1 : wz0;
                    float4 wn = half ? wn1 : wn0;
                    const float wrr[4] = {wr.x, wr.y, wr.z, wr.w};
                    const float wzz[4] = {wz.x, wz.y, wz.z, wz.w};
                    const float wnn[4] = {wn.x, wn.y, wn.z, wn.w};
#pragma unroll
                    for (int c = 0; c < 4; c++) {
                        int k = 4 * (kc + half) + c;
                        ulonglong2 hA = *(const ulonglong2*)&hrp0[k * 4];
                        ulonglong2 hB = *(const ulonglong2*)&hrp0[k * 4 + 2];
                        u64 wrd = pk2(wrr[c], wrr[c]);
                        u64 wzd = pk2(wzz[c], wzz[c]);
                        u64 wnd = pk2(wnn[c], wnn[c]);
                        aR[0] = fma2(wrd, hA.x, aR[0]); aR[1] = fma2(wrd, hA.y, aR[1]);
                        aR[2] = fma2(wrd, hB.x, aR[2]); aR[3] = fma2(wrd, hB.y, aR[3]);
                        aZ[0] = fma2(wzd, hA.x, aZ[0]); aZ[1] = fma2(wzd, hA.y, aZ[1]);
                        aZ[2] = fma2(wzd, hB.x, aZ[2]); aZ[3] = fma2(wzd, hB.y, aZ[3]);
                        aN[0] = fma2(wnd, hA.x, aN[0]); aN[1] = fma2(wnd, hA.y, aN[1]);
                        aN[2] = fma2(wnd, hB.x, aN[2]); aN[3] = fma2(wnd, hB.y, aN[3]);
                    }
                }
                wr0 = nr0; wz0 = nz0; wn0 = nn0;
                wr1 = nr1; wz1 = nz1; wn1 = nn1;
            }
        } else {
            // B-hN: n-gate of Whh1 over OLD h1, col jB, 8 rows
            u64 hN[4];
#pragma unroll
            for (int rp = 0; rp < 4; rp++) hN[rp] = bhnd;
            float4 cw = wB2n[0];
            for (int kc = 0; kc < 32; kc++) {
                float4 nw = wB2n[((kc + 1) & 31) * 384];
                const float w4[4] = {cw.x, cw.y, cw.z, cw.w};
#pragma unroll
                for (int c = 0; c < 4; c++) {
                    int k = 4 * kc + c;
                    ulonglong2 hA = *(const ulonglong2*)&hrp1[k * 4];
                    ulonglong2 hB = *(const ulonglong2*)&hrp1[k * 4 + 2];
                    u64 wd = pk2(w4[c], w4[c]);
                    hN[0] = fma2(wd, hA.x, hN[0]); hN[1] = fma2(wd, hA.y, hN[1]);
                    hN[2] = fma2(wd, hB.x, hN[2]); hN[3] = fma2(wd, hB.y, hN[3]);
                }
                cw = nw;
            }
#pragma unroll
            for (int rp = 0; rp < 4; rp++) bhn[jB * 4 + rp] = hN[rp];
            // C-hN: first 32 of these threads
            if (jB < 32) {
                u64 hC[4];
                u64 bc = pk2(bhh2[64 + jB], bhh2[64 + jB]);
#pragma unroll
                for (int rp = 0; rp < 4; rp++) hC[rp] = bc;
                const float4* wcn = g_wC2 + 64 + jB;
                for (int kc = 0; kc < 8; kc++) {
                    float4 w = wcn[kc * 96];
                    const float w4[4] = {w.x, w.y, w.z, w.w};
#pragma unroll
                    for (int c = 0; c < 4; c++) {
                        int k = 4 * kc + c;
                        ulonglong2 hA = *(const ulonglong2*)&hrp2[k * 4];
                        ulonglong2 hB = *(const ulonglong2*)&hrp2[k * 4 + 2];
                        u64 wd = pk2(w4[c], w4[c]);
                        hC[0] = fma2(wd, hA.x, hC[0]); hC[1] = fma2(wd, hA.y, hC[1]);
                        hC[2] = fma2(wd, hB.x, hC[2]); hC[3] = fma2(wd, hB.y, hC[3]);
                    }
                }
#pragma unroll
                for (int rp = 0; rp < 4; rp++) chn[jB * 4 + rp] = hC[rp];
            }
        }
        __syncthreads();

        // ======== Phase A elementwise (owners) ========
        if (tid < 256) {
#pragma unroll
            for (int rp = 0; rp < 4; rp++) {
                float r0e, r1e, z0e, z1e, n0e, n1e, h0e, h1e;
                up2(aR[rp], r0e, r1e); up2(aZ[rp], z0e, z1e); up2(aN[rp], n0e, n1e);
                float gi0 = g_G0[(size_t)tokrow[2 * rp] * 768 + 512 + tA];
                float gi1 = g_G0[(size_t)tokrow[2 * rp + 1] * 768 + 512 + tA];
                up2(hrp0[tA * 4 + rp], h0e, h1e);
                float rg0 = sigf(r0e), rg1 = sigf(r1e);
                float zg0 = sigf(z0e), zg1 = sigf(z1e);
                float ng0 = tanh_(gi0 + rg0 * n0e), ng1 = tanh_(gi1 + rg1 * n1e);
                float v0 = (1.0f - zg0) * ng0 + zg0 * h0e;
                float v1 = (1.0f - zg1) * ng1 + zg1 * h1e;
                hrp0[tA * 4 + rp] = pk2(v0, v1);
            }
        }
        __syncthreads();

        // ======== Window 2: phase B gate-col accumulation (384 threads, 0-dup) ========
        {
            u64 acc[4];
#pragma unroll
            for (int rp = 0; rp < 4; rp++) acc[rp] = bBd;
            float4 cw = wB1p[0];
            for (int kc = 0; kc < 64; kc++) {
                float4 nw = wB1p[((kc + 1) & 63) * 384];
                const float w4[4] = {cw.x, cw.y, cw.z, cw.w};
#pragma unroll
                for (int c = 0; c < 4; c++) {
                    int k = 4 * kc + c;
                    ulonglong2 hA = *(const ulonglong2*)&hrp0[k * 4];
                    ulonglong2 hB = *(const ulonglong2*)&hrp0[k * 4 + 2];
                    u64 wd = pk2(w4[c], w4[c]);
                    acc[0] = fma2(wd, hA.x, acc[0]); acc[1] = fma2(wd, hA.y, acc[1]);
                    acc[2] = fma2(wd, hB.x, acc[2]); acc[3] = fma2(wd, hB.y, acc[3]);
                }
                cw = nw;
            }
            if (gB < 2) {
                float4 cw2 = wB2p[0];
                for (int kc = 0; kc < 32; kc++) {
                    float4 nw2 = wB2p[((kc + 1) & 31) * 384];
                    const float w4[4] = {cw2.x, cw2.y, cw2.z, cw2.w};
#pragma unroll
                    for (int c = 0; c < 4; c++) {
                        int k = 4 * kc + c;
                        ulonglong2 hA = *(const ulonglong2*)&hrp1[k * 4];
                        ulonglong2 hB = *(const ulonglong2*)&hrp1[k * 4 + 2];
                        u64 wd = pk2(w4[c], w4[c]);
                        acc[0] = fma2(wd, hA.x, acc[0]); acc[1] = fma2(wd, hA.y, acc[1]);
                        acc[2] = fma2(wd, hB.x, acc[2]); acc[3] = fma2(wd, hB.y, acc[3]);
                    }
                    cw2 = nw2;
                }
            }
#pragma unroll
            for (int rp = 0; rp < 4; rp++) cmb[gB * 512 + jB * 4 + rp] = acc[rp];
        }
        __syncthreads();

        // ======== Phase B combine: 512 row-pair items ========
        for (int q = tid; q < 512; q += NTHR) {
            int j = q >> 2, rp = q & 3;
            u64 rv = cmb[j * 4 + rp];
            u64 zv = cmb[512 + j * 4 + rp];
            u64 iv = cmb[1024 + j * 4 + rp];
            u64 hv = bhn[j * 4 + rp];
            float r0e, r1e, z0e, z1e, i0e, i1e, n0e, n1e, h0e, h1e;
            up2(rv, r0e, r1e); up2(zv, z0e, z1e);
            up2(iv, i0e, i1e); up2(hv, n0e, n1e);
            up2(hrp1[j * 4 + rp], h0e, h1e);
            float rg0 = sigf(r0e), rg1 = sigf(r1e);
            float zg0 = sigf(z0e), zg1 = sigf(z1e);
            float ng0 = tanh_(i0e + rg0 * n0e), ng1 = tanh_(i1e + rg1 * n1e);
            float v0 = (1.0f - zg0) * ng0 + zg0 * h0e;
            float v1 = (1.0f - zg1) * ng1 + zg1 * h1e;
            hrp1[j * 4 + rp] = pk2(v0, v1);
        }
        __syncthreads();

        // ======== Window 3: phase C gate-col accumulation (96 threads) ========
        if (tid < 96) {
            u64 acc[4];
#pragma unroll
            for (int rp = 0; rp < 4; rp++) acc[rp] = bCd;
            for (int kc = 0; kc < 32; kc++) {
                float4 w = wC1p[kc * 96];
                const float w4[4] = {w.x, w.y, w.z, w.w};
#pragma unroll
                for (int c = 0; c < 4; c++) {
                    int k = 4 * kc + c;
                    ulonglong2 hA = *(const ulonglong2*)&hrp1[k * 4];
                    ulonglong2 hB = *(const ulonglong2*)&hrp1[k * 4 + 2];
                    u64 wd = pk2(w4[c], w4[c]);
                    acc[0] = fma2(wd, hA.x, acc[0]); acc[1] = fma2(wd, hA.y, acc[1]);
                    acc[2] = fma2(wd, hB.x, acc[2]); acc[3] = fma2(wd, hB.y, acc[3]);
                }
            }
            if (gb3 < 2) {
                for (int kc = 0; kc < 8; kc++) {
                    float4 w = wC2p[kc * 96];
                    const float w4[4] = {w.x, w.y, w.z, w.w};
#pragma unroll
                    for (int c = 0; c < 4; c++) {
                        int k = 4 * kc + c;
                        ulonglong2 hA = *(const ulonglong2*)&hrp2[k * 4];
                        ulonglong2 hB = *(const ulonglong2*)&hrp2[k * 4 + 2];
                        u64 wd = pk2(w4[c], w4[c]);
                        acc[0] = fma2(wd, hA.x, acc[0]); acc[1] = fma2(wd, hA.y, acc[1]);
                        acc[2] = fma2(wd, hB.x, acc[2]); acc[3] = fma2(wd, hB.y, acc[3]);
                    }
                }
            }
#pragma unroll
            for (int rp = 0; rp < 4; rp++) cmb[gb3 * 128 + jb3 * 4 + rp] = acc[rp];
        }
        __syncthreads();

        // ======== Phase C combine: 128 row-pair items ========
        if (tid < 128) {
            int j = tid >> 2, rp = tid & 3;
            u64 rv = cmb[j * 4 + rp];
            u64 zv = cmb[128 + j * 4 + rp];
            u64 iv = cmb[256 + j * 4 + rp];
            u64 hv = chn[j * 4 + rp];
            float r0e, r1e, z0e, z1e, i0e, i1e, n0e, n1e, h0e, h1e;
            up2(rv, r0e, r1e); up2(zv, z0e, z1e);
            up2(iv, i0e, i1e); up2(hv, n0e, n1e);
            up2(hrp2[j * 4 + rp], h0e, h1e);
            float rg0 = sigf(r0e), rg1 = sigf(r1e);
            float zg0 = sigf(z0e), zg1 = sigf(z1e);
            float ng0 = tanh_(i0e + rg0 * n0e), ng1 = tanh_(i1e + rg1 * n1e);
            float v0 = (1.0f - zg0) * ng0 + zg0 * h0e;
            float v1 = (1.0f - zg1) * ng1 + zg1 * h1e;
            hrp2[j * 4 + rp] = pk2(v0, v1);
        }
        __syncthreads();

        // ======== Phase D: projection + argmax (single pass, 328 < 384) ========
        if (tid < BT * Vsz) {
            const float* h2f = (const float*)hrp2;
            int row = tid / Vsz, j = tid - row * Vsz;
            float acc = b_proj[j];
#pragma unroll
            for (int k = 0; k < 32; k++)
                acc += g_WprojT[k * Vsz + j] * h2f[k * 8 + row];
            out[((size_t)(b0 + row) * Ssz + st) * Vsz + j] = acc;
            lg[row][j] = acc;
        }
        __syncthreads();
        if (tid < BT && pred) {
            float best = lg[tid][0];
            int bi = 0;
#pragma unroll 1
            for (int j = 1; j < Vsz; j++) {
                float v = lg[tid][j];
                if (v > best) { best = v; bi = j; }
            }
            pred[(size_t)(b0 + tid) * Ssz + st] = (float)bi;
        }
        __syncthreads();
    }
}

// ---------------- launch ----------------
extern "C" void kernel_launch(void* const* d_in, const int* in_sizes, int n_in,
                              void* d_out, int out_size) {
    const float* latent  = (const float*)d_in[0];
    const int*   tokens  = (const int*)d_in[1];
    const float* W_emb   = (const float*)d_in[2];
    const float* b_emb   = (const float*)d_in[3];
    const float* W_init  = (const float*)d_in[4];
    const float* b_init  = (const float*)d_in[5];
    const float* Wih0    = (const float*)d_in[6];
    const float* Whh0    = (const float*)d_in[7];
    const float* bih0    = (const float*)d_in[8];
    const float* bhh0    = (const float*)d_in[9];
    const float* Wih1    = (const float*)d_in[10];
    const float* Whh1    = (const float*)d_in[11];
    const float* bih1    = (const float*)d_in[12];
    const float* bhh1    = (const float*)d_in[13];
    const float* Wih2    = (const float*)d_in[14];
    const float* Whh2    = (const float*)d_in[15];
    const float* bih2    = (const float*)d_in[16];
    const float* bhh2    = (const float*)d_in[17];
    const float* W_proj  = (const float*)d_in[18];
    const float* b_proj  = (const float*)d_in[19];

    float* out = (float*)d_out;
    size_t logits_elems = (size_t)Bsz * Ssz * Vsz;
    float* pred = ((size_t)out_size >= logits_elems + (size_t)Bsz * Ssz)
                      ? out + logits_elems : nullptr;

    k_prep<<<256, 256>>>(latent, W_emb, b_emb, W_init, b_init, Wih0, bih0, Whh0,
                         Wih1, Whh1, Wih2, Whh2, W_proj);
    k_main<<<NCTA, NTHR>>>(tokens, bhh0, bih1, bhh1, bih2, bhh2, b_proj, out, pred);
}